// round 15
// baseline (speedup 1.0000x reference)
#include <cuda_runtime.h>
#include <cstdint>
#include <cstddef>

#define NNODE 50000
#define NEDGE 800000
#define DD 128     // node feature dim
#define DE 64      // edge feature dim
#define HH 256     // hidden dim (2*D)
#define BN_EPS 1e-5f

// ---------------- device scratch (static; no allocations allowed) ----------------
__device__ float g_hpre[(size_t)NNODE * DD];
__device__ float g_y1[(size_t)NNODE * HH];
__device__ float g_WeT[DE * DD];
__device__ float g_W1T[DD * HH];
__device__ float g_W2T[HH * DD];
__device__ int   g_src[NEDGE];
__device__ int   g_dst[NEDGE];
__device__ float g_sum1[HH], g_sq1[HH], g_sum2[DD], g_sq2[DD];
__device__ float g_scale1[HH], g_shift1[HH], g_scale2[DD], g_shift2[DD];

__device__ __forceinline__ void red_add_v4(float* a, float x, float y, float z, float w) {
    asm volatile("red.global.add.v4.f32 [%0], {%1,%2,%3,%4};"
                 :: "l"(a), "f"(x), "f"(y), "f"(z), "f"(w) : "memory");
}

// packed fp32x2 helpers (sm_100+)
__device__ __forceinline__ unsigned long long bcast2(float a) {
    unsigned long long r;
    unsigned int u = __float_as_uint(a);
    asm("mov.b64 %0, {%1, %1};" : "=l"(r) : "r"(u));
    return r;
}
__device__ __forceinline__ void ffma2(unsigned long long& d, unsigned long long a,
                                      unsigned long long b) {
    asm("fma.rn.f32x2 %0, %1, %2, %0;" : "+l"(d) : "l"(a), "l"(b));
}
__device__ __forceinline__ float2 up2(unsigned long long v) {
    float2 f;
    f.x = __uint_as_float((unsigned int)v);
    f.y = __uint_as_float((unsigned int)(v >> 32));
    return f;
}

// ---------------- 1) decode edge_index (int64 or int32, detected on device) -----
__global__ void k_decode(const int* __restrict__ ei) {
    bool is64 = ((ei[1] | ei[3] | ei[5] | ei[7] | ei[9] | ei[11] | ei[13] | ei[15]) == 0);
    int stride = gridDim.x * blockDim.x;
    for (int i = blockIdx.x * blockDim.x + threadIdx.x; i < NEDGE; i += stride) {
        int s, d;
        if (is64) {
            const long long* p = (const long long*)ei;
            s = (int)p[i];
            d = (int)p[NEDGE + i];
        } else {
            s = ei[i];
            d = ei[NEDGE + i];
        }
        g_src[i] = s;
        g_dst[i] = d;
    }
}

// ---------------- 2) transposes + zero stats ------------------------------------
__global__ void k_misc(const float* __restrict__ We, const float* __restrict__ W1,
                       const float* __restrict__ W2) {
    int stride = gridDim.x * blockDim.x;
    int t0 = blockIdx.x * blockDim.x + threadIdx.x;
    for (int i = t0; i < DE * DD; i += stride) { int k = i / DD, j = i % DD; g_WeT[i] = We[j * DE + k]; }
    for (int i = t0; i < DD * HH; i += stride) { int k = i / HH, j = i % HH; g_W1T[i] = W1[j * DD + k]; }
    for (int i = t0; i < HH * DD; i += stride) { int k = i / DD, j = i % DD; g_W2T[i] = W2[j * HH + k]; }
    for (int i = t0; i < HH; i += stride) { g_sum1[i] = 0.f; g_sq1[i] = 0.f; }
    for (int i = t0; i < DD; i += stride) { g_sum2[i] = 0.f; g_sq2[i] = 0.f; }
}

// ---------------- 3) hpre = (1+eps) * x -----------------------------------------
__global__ void k_hpre(const float* __restrict__ x, const float* __restrict__ epsp) {
    float c = 1.0f + *epsp;
    int stride = gridDim.x * blockDim.x;
    const float4* x4 = (const float4*)x;
    float4* h4 = (float4*)g_hpre;
    for (int i = blockIdx.x * blockDim.x + threadIdx.x; i < NNODE * DD / 4; i += stride) {
        float4 v = x4[i];
        v.x *= c; v.y *= c; v.z *= c; v.w *= c;
        h4[i] = v;
    }
}

// ---------------- 4) edge kernel: FFMA2 GEMM, warp-footprint 32e x 64c -----------
// Per CTA: 128 edges x 128 cols, K=64; 8 warps each covering 32 edges x 64 cols
// (E+C=96 vs 144 for 16x128) -> 33% less smem traffic after broadcast dedup.
// Lane: e_sub = lane>>3 (8-edge group), c_sub = lane&7 (8-col group).
// sA [128][80]: row rotated by ((row>>3)&3)*4 -> the 4 broadcast addrs per instr
//               (rows 8 apart, same bank base) land on disjoint bank quads.
// sB h-split:   col g*8+h*4+j stored at k*128 + h*64 + g*4 -> a warp's 8 group
//               reads at fixed h hit banks {0,4,..,28}: one 128B wavefront.
#define AEPAD 80
#define SM_A_FLOATS (128 * AEPAD)      // 10240
#define SM_B_FLOATS (64 * 128)         // 8192
#define SM_IDX_F (SM_A_FLOATS + SM_B_FLOATS)
#define SM_EDGE_TOTAL ((SM_IDX_F + 256) * 4)   // 74752 B; x2 CTAs = 149.5 KB

__global__ __launch_bounds__(256, 2) void k_edge(const float* __restrict__ ea,
                                                 const float* __restrict__ x,
                                                 const float* __restrict__ be) {
    extern __shared__ float sm[];
    float* sA = sm;
    float* sB = sm + SM_A_FLOATS;
    int* sSrc = (int*)(sm + SM_IDX_F);
    int* sDst = sSrc + 128;

    int tid = threadIdx.x;
    int wid = tid >> 5, lane = tid & 31;
    int e_sub = lane >> 3, c_sub = lane & 7;
    int e0 = blockIdx.x * 128;

    // A fill: 128 edges x 64 k, rotated rows
#pragma unroll
    for (int r = 0; r < 8; r++) {
        int i = tid + 256 * r;             // 0..2047
        int row = i >> 4, c4 = i & 15;
        float4 v = *(const float4*)(ea + (size_t)(e0 + row) * DE + c4 * 4);
        *(float4*)&sA[row * AEPAD + ((row >> 3) & 3) * 4 + c4 * 4] = v;
    }
    // B fill: WeT[k][j] -> h-split layout k*128 + (c4&1)*64 + (c4>>1)*4
    const float4* gW = (const float4*)g_WeT;
#pragma unroll
    for (int r = 0; r < 8; r++) {
        int i = tid + 256 * r;             // 0..2047 float4s
        int k = i >> 5, c4 = i & 31;
        float4 v = gW[i];
        *(float4*)&sB[k * 128 + (c4 & 1) * 64 + (c4 >> 1) * 4] = v;
    }
    if (tid < 128) { sSrc[tid] = g_src[e0 + tid]; sDst[tid] = g_dst[e0 + tid]; }
    __syncthreads();

    int erow0 = (wid & 3) * 32 + e_sub * 8;      // thread's 8 contiguous edges
    int g = (wid >> 2) * 8 + c_sub;              // col group 0..15 (cols g*8..g*8+7)
    int tx8 = g * 8;
    const float* aBase = sA + erow0 * AEPAD + e_sub * 4;   // rot = e_sub*4 (matches fill)
    const float* bBase = sB + g * 4;

    unsigned long long acc[8][4];
#pragma unroll
    for (int i = 0; i < 8; i++)
#pragma unroll
        for (int j = 0; j < 4; j++) acc[i][j] = 0ull;

#pragma unroll
    for (int k = 0; k < DE; k += 4) {
        // B rows k..k+3 for this thread's 8 cols: h=0 chunk (cols 0-3) + h=1 (+64)
        unsigned long long b[4][4];
#pragma unroll
        for (int kk = 0; kk < 4; kk++) {
            const float* brow = bBase + (k + kk) * 128;
            ulonglong2 t0 = *(const ulonglong2*)brow;          // cols 0-1, 2-3
            ulonglong2 t1 = *(const ulonglong2*)(brow + 64);   // cols 4-5, 6-7
            b[kk][0] = t0.x; b[kk][1] = t0.y; b[kk][2] = t1.x; b[kk][3] = t1.y;
        }
#pragma unroll
        for (int i = 0; i < 8; i++) {
            float4 a4 = *(const float4*)(aBase + i * AEPAD + k);
#pragma unroll
            for (int kk = 0; kk < 4; kk++) {
                unsigned long long a2 = bcast2(((const float*)&a4)[kk]);
                ffma2(acc[i][0], a2, b[kk][0]);
                ffma2(acc[i][1], a2, b[kk][1]);
                ffma2(acc[i][2], a2, b[kk][2]);
                ffma2(acc[i][3], a2, b[kk][3]);
            }
        }
    }

    float4 be0 = *(const float4*)(be + tx8);
    float4 be1 = *(const float4*)(be + tx8 + 4);
#pragma unroll
    for (int i = 0; i < 8; i++) {
        int el = erow0 + i;
        int s = sSrc[el];
        int d = sDst[el];
        const float4* xr = (const float4*)(x + (size_t)s * DD + tx8);
        float4 x0 = xr[0], x1 = xr[1];
        float2 p0 = up2(acc[i][0]), p1 = up2(acc[i][1]);
        float2 p2 = up2(acc[i][2]), p3 = up2(acc[i][3]);
        float* dptr = g_hpre + (size_t)d * DD + tx8;
        red_add_v4(dptr,
                   fmaxf(p0.x + x0.x + be0.x, 0.f),
                   fmaxf(p0.y + x0.y + be0.y, 0.f),
                   fmaxf(p1.x + x0.z + be0.z, 0.f),
                   fmaxf(p1.y + x0.w + be0.w, 0.f));
        red_add_v4(dptr + 4,
                   fmaxf(p2.x + x1.x + be1.x, 0.f),
                   fmaxf(p2.y + x1.y + be1.y, 0.f),
                   fmaxf(p3.x + x1.z + be1.z, 0.f),
                   fmaxf(p3.y + x1.w + be1.w, 0.f));
    }
}

// ---------------- 5) GEMM1: y1 = hpre @ W1^T + b1, accumulate BN stats ----------
__global__ __launch_bounds__(256, 2) void k_gemm1(const float* __restrict__ bias) {
    __shared__ float As[128 * 36];
    __shared__ float Bs[32 * 128];
    __shared__ float sSum[128];
    __shared__ float sSq[128];
    int tid = threadIdx.x;
    int m0 = blockIdx.x * 128;
    int n0 = blockIdx.y * 128;
    int tx8 = (tid & 15) * 8;
    int ty8 = (tid >> 4) * 8;
    unsigned long long acc[8][4];
#pragma unroll
    for (int i = 0; i < 8; i++)
#pragma unroll
        for (int j = 0; j < 4; j++) acc[i][j] = 0ull;

    for (int kc = 0; kc < DD; kc += 32) {
#pragma unroll
        for (int r = 0; r < 4; r++) {
            int idx = tid + 256 * r;
            int row = idx >> 3, c4 = idx & 7;
            int m = m0 + row;
            float4 v = make_float4(0.f, 0.f, 0.f, 0.f);
            if (m < NNODE) v = *(const float4*)&g_hpre[(size_t)m * DD + kc + c4 * 4];
            *(float4*)&As[row * 36 + c4 * 4] = v;
        }
#pragma unroll
        for (int r = 0; r < 4; r++) {
            int idx = tid + 256 * r;
            int k = idx >> 5, c4 = idx & 31;
            *(float4*)&Bs[k * 128 + c4 * 4] = *(const float4*)&g_W1T[(size_t)(kc + k) * HH + n0 + c4 * 4];
        }
        __syncthreads();
#pragma unroll
        for (int k = 0; k < 32; k += 4) {
            unsigned long long b[4][4];
#pragma unroll
            for (int kk = 0; kk < 4; kk++) {
                const unsigned long long* bp = (const unsigned long long*)&Bs[(k + kk) * 128 + tx8];
                b[kk][0] = bp[0]; b[kk][1] = bp[1]; b[kk][2] = bp[2]; b[kk][3] = bp[3];
            }
#pragma unroll
            for (int i = 0; i < 8; i++) {
                float4 a4 = *(const float4*)&As[(ty8 + i) * 36 + k];
#pragma unroll
                for (int kk = 0; kk < 4; kk++) {
                    unsigned long long a2 = bcast2(((const float*)&a4)[kk]);
                    ffma2(acc[i][0], a2, b[kk][0]);
                    ffma2(acc[i][1], a2, b[kk][1]);
                    ffma2(acc[i][2], a2, b[kk][2]);
                    ffma2(acc[i][3], a2, b[kk][3]);
                }
            }
        }
        __syncthreads();
    }

    float4 bb0 = *(const float4*)&bias[n0 + tx8];
    float4 bb1 = *(const float4*)&bias[n0 + tx8 + 4];
    float bv[8] = {bb0.x, bb0.y, bb0.z, bb0.w, bb1.x, bb1.y, bb1.z, bb1.w};
    float lsum[8], lsq[8];
#pragma unroll
    for (int j = 0; j < 8; j++) { lsum[j] = 0.f; lsq[j] = 0.f; }
#pragma unroll
    for (int i = 0; i < 8; i++) {
        int m = m0 + ty8 + i;
        if (m < NNODE) {
            float2 pr[4] = {up2(acc[i][0]), up2(acc[i][1]), up2(acc[i][2]), up2(acc[i][3])};
            float v[8];
#pragma unroll
            for (int j = 0; j < 8; j++) {
                float a = (j & 1) ? pr[j >> 1].y : pr[j >> 1].x;
                v[j] = a + bv[j];
                lsum[j] += v[j];
                lsq[j] += v[j] * v[j];
            }
            float4* o = (float4*)&g_y1[(size_t)m * HH + n0 + tx8];
            o[0] = make_float4(v[0], v[1], v[2], v[3]);
            o[1] = make_float4(v[4], v[5], v[6], v[7]);
        }
    }
    if (tid < 128) { sSum[tid] = 0.f; sSq[tid] = 0.f; }
    __syncthreads();
#pragma unroll
    for (int j = 0; j < 8; j++) {
        atomicAdd(&sSum[tx8 + j], lsum[j]);
        atomicAdd(&sSq[tx8 + j], lsq[j]);
    }
    __syncthreads();
    if (tid < 128) {
        atomicAdd(&g_sum1[n0 + tid], sSum[tid]);
        atomicAdd(&g_sq1[n0 + tid], sSq[tid]);
    }
}

// ---------------- 6) fold BN1 stats into scale/shift ----------------------------
__global__ void k_stat1(const float* __restrict__ g, const float* __restrict__ beta) {
    int j = threadIdx.x;
    if (j < HH) {
        float mu = g_sum1[j] / (float)NNODE;
        float var = g_sq1[j] / (float)NNODE - mu * mu;
        float sc = g[j] * rsqrtf(var + BN_EPS);
        g_scale1[j] = sc;
        g_shift1[j] = beta[j] - mu * sc;
    }
}

// ---------------- 7) GEMM2: out = relu(bn1(y1)) @ W2^T + b2, accumulate stats ---
__global__ __launch_bounds__(256, 2) void k_gemm2(const float* __restrict__ bias,
                                                  float* __restrict__ out) {
    __shared__ float As[128 * 36];
    __shared__ float Bs[32 * 128];
    __shared__ float sSum[128];
    __shared__ float sSq[128];
    int tid = threadIdx.x;
    int m0 = blockIdx.x * 128;
    int tx8 = (tid & 15) * 8;
    int ty8 = (tid >> 4) * 8;
    unsigned long long acc[8][4];
#pragma unroll
    for (int i = 0; i < 8; i++)
#pragma unroll
        for (int j = 0; j < 4; j++) acc[i][j] = 0ull;

    for (int kc = 0; kc < HH; kc += 32) {
#pragma unroll
        for (int r = 0; r < 4; r++) {
            int idx = tid + 256 * r;
            int row = idx >> 3, c4 = idx & 7;
            int m = m0 + row;
            int col = kc + c4 * 4;
            float4 v = make_float4(0.f, 0.f, 0.f, 0.f);
            if (m < NNODE) v = *(const float4*)&g_y1[(size_t)m * HH + col];
            float4 sc = *(const float4*)&g_scale1[col];
            float4 sh = *(const float4*)&g_shift1[col];
            v.x = fmaxf(fmaf(v.x, sc.x, sh.x), 0.f);
            v.y = fmaxf(fmaf(v.y, sc.y, sh.y), 0.f);
            v.z = fmaxf(fmaf(v.z, sc.z, sh.z), 0.f);
            v.w = fmaxf(fmaf(v.w, sc.w, sh.w), 0.f);
            *(float4*)&As[row * 36 + c4 * 4] = v;
        }
#pragma unroll
        for (int r = 0; r < 4; r++) {
            int idx = tid + 256 * r;
            int k = idx >> 5, c4 = idx & 31;
            *(float4*)&Bs[k * 128 + c4 * 4] = *(const float4*)&g_W2T[(size_t)(kc + k) * DD + c4 * 4];
        }
        __syncthreads();
#pragma unroll
        for (int k = 0; k < 32; k += 4) {
            unsigned long long b[4][4];
#pragma unroll
            for (int kk = 0; kk < 4; kk++) {
                const unsigned long long* bp = (const unsigned long long*)&Bs[(k + kk) * 128 + tx8];
                b[kk][0] = bp[0]; b[kk][1] = bp[1]; b[kk][2] = bp[2]; b[kk][3] = bp[3];
            }
#pragma unroll
            for (int i = 0; i < 8; i++) {
                float4 a4 = *(const float4*)&As[(ty8 + i) * 36 + k];
#pragma unroll
                for (int kk = 0; kk < 4; kk++) {
                    unsigned long long a2 = bcast2(((const float*)&a4)[kk]);
                    ffma2(acc[i][0], a2, b[kk][0]);
                    ffma2(acc[i][1], a2, b[kk][1]);
                    ffma2(acc[i][2], a2, b[kk][2]);
                    ffma2(acc[i][3], a2, b[kk][3]);
                }
            }
        }
        __syncthreads();
    }

    float4 bb0 = *(const float4*)&bias[tx8];
    float4 bb1 = *(const float4*)&bias[tx8 + 4];
    float bv[8] = {bb0.x, bb0.y, bb0.z, bb0.w, bb1.x, bb1.y, bb1.z, bb1.w};
    float lsum[8], lsq[8];
#pragma unroll
    for (int j = 0; j < 8; j++) { lsum[j] = 0.f; lsq[j] = 0.f; }
#pragma unroll
    for (int i = 0; i < 8; i++) {
        int m = m0 + ty8 + i;
        if (m < NNODE) {
            float2 pr[4] = {up2(acc[i][0]), up2(acc[i][1]), up2(acc[i][2]), up2(acc[i][3])};
            float v[8];
#pragma unroll
            for (int j = 0; j < 8; j++) {
                float a = (j & 1) ? pr[j >> 1].y : pr[j >> 1].x;
                v[j] = a + bv[j];
                lsum[j] += v[j];
                lsq[j] += v[j] * v[j];
            }
            float4* o = (float4*)&out[(size_t)m * DD + tx8];
            o[0] = make_float4(v[0], v[1], v[2], v[3]);
            o[1] = make_float4(v[4], v[5], v[6], v[7]);
        }
    }
    if (tid < 128) { sSum[tid] = 0.f; sSq[tid] = 0.f; }
    __syncthreads();
#pragma unroll
    for (int j = 0; j < 8; j++) {
        atomicAdd(&sSum[tx8 + j], lsum[j]);
        atomicAdd(&sSq[tx8 + j], lsq[j]);
    }
    __syncthreads();
    if (tid < 128) {
        atomicAdd(&g_sum2[tid], sSum[tid]);
        atomicAdd(&g_sq2[tid], sSq[tid]);
    }
}

// ---------------- 8) fold BN2 stats --------------------------------------------
__global__ void k_stat2(const float* __restrict__ g, const float* __restrict__ beta) {
    int j = threadIdx.x;
    if (j < DD) {
        float mu = g_sum2[j] / (float)NNODE;
        float var = g_sq2[j] / (float)NNODE - mu * mu;
        float sc = g[j] * rsqrtf(var + BN_EPS);
        g_scale2[j] = sc;
        g_shift2[j] = beta[j] - mu * sc;
    }
}

// ---------------- 9) final elementwise: out = relu(bn2(out)) --------------------
__global__ void k_final(float* __restrict__ out) {
    int stride = gridDim.x * blockDim.x;
    float4* o4 = (float4*)out;
    for (int i = blockIdx.x * blockDim.x + threadIdx.x; i < NNODE * DD / 4; i += stride) {
        int col = (i & 31) * 4;
        float4 sc = *(const float4*)&g_scale2[col];
        float4 sh = *(const float4*)&g_shift2[col];
        float4 v = o4[i];
        v.x = fmaxf(fmaf(v.x, sc.x, sh.x), 0.f);
        v.y = fmaxf(fmaf(v.y, sc.y, sh.y), 0.f);
        v.z = fmaxf(fmaf(v.z, sc.z, sh.z), 0.f);
        v.w = fmaxf(fmaf(v.w, sc.w, sh.w), 0.f);
        o4[i] = v;
    }
}

// ---------------- launcher ------------------------------------------------------
extern "C" void kernel_launch(void* const* d_in, const int* in_sizes, int n_in,
                              void* d_out, int out_size) {
    const float* x   = (const float*)d_in[0];
    const int*   ei  = (const int*)d_in[1];
    const float* ea  = (const float*)d_in[2];
    const float* We  = (const float*)d_in[3];
    const float* be  = (const float*)d_in[4];
    const float* W1  = (const float*)d_in[5];
    const float* b1  = (const float*)d_in[6];
    const float* g1  = (const float*)d_in[7];
    const float* be1 = (const float*)d_in[8];
    const float* W2  = (const float*)d_in[9];
    const float* b2  = (const float*)d_in[10];
    const float* g2  = (const float*)d_in[11];
    const float* be2 = (const float*)d_in[12];
    const float* eps = (const float*)d_in[13];
    float* out = (float*)d_out;

    cudaFuncSetAttribute(k_edge, cudaFuncAttributeMaxDynamicSharedMemorySize, SM_EDGE_TOTAL);

    k_decode<<<1024, 256>>>(ei);
    k_misc<<<64, 256>>>(We, W1, W2);
    k_hpre<<<2048, 256>>>(x, eps);
    k_edge<<<NEDGE / 128, 256, SM_EDGE_TOTAL>>>(ea, x, be);
    dim3 g1grid((NNODE + 127) / 128, 2);
    k_gemm1<<<g1grid, 256>>>(b1);
    k_stat1<<<1, 256>>>(g1, be1);
    k_gemm2<<<(NNODE + 127) / 128, 256>>>(b2, out);
    k_stat2<<<1, 128>>>(g2, be2);
    k_final<<<2048, 256>>>(out);
}

// round 17
// speedup vs baseline: 1.5512x; 1.5512x over previous
#include <cuda_runtime.h>
#include <cstdint>
#include <cstddef>

#define NNODE 50000
#define NEDGE 800000
#define DD 128     // node feature dim
#define DE 64      // edge feature dim
#define HH 256     // hidden dim (2*D)
#define BN_EPS 1e-5f

// ---------------- device scratch (static; no allocations allowed) ----------------
__device__ float g_hpre[(size_t)NNODE * DD];
__device__ float g_y1[(size_t)NNODE * HH];
__device__ float g_WeT[DE * DD];
__device__ float g_W1T[DD * HH];
__device__ float g_W2T[HH * DD];
__device__ int   g_src[NEDGE];
__device__ int   g_dst[NEDGE];
__device__ float g_sum1[HH], g_sq1[HH], g_sum2[DD], g_sq2[DD];
__device__ float g_scale1[HH], g_shift1[HH], g_scale2[DD], g_shift2[DD];

__device__ __forceinline__ void red_add_v4(float* a, float x, float y, float z, float w) {
    asm volatile("red.global.add.v4.f32 [%0], {%1,%2,%3,%4};"
                 :: "l"(a), "f"(x), "f"(y), "f"(z), "f"(w) : "memory");
}

// packed fp32x2 helpers (sm_100+)
__device__ __forceinline__ unsigned long long bcast2(float a) {
    unsigned long long r;
    unsigned int u = __float_as_uint(a);
    asm("mov.b64 %0, {%1, %1};" : "=l"(r) : "r"(u));
    return r;
}
__device__ __forceinline__ void ffma2(unsigned long long& d, unsigned long long a,
                                      unsigned long long b) {
    asm("fma.rn.f32x2 %0, %1, %2, %0;" : "+l"(d) : "l"(a), "l"(b));
}
__device__ __forceinline__ float2 up2(unsigned long long v) {
    float2 f;
    f.x = __uint_as_float((unsigned int)v);
    f.y = __uint_as_float((unsigned int)(v >> 32));
    return f;
}

// ---------------- 1) decode edge_index (int64 or int32, detected on device) -----
__global__ void k_decode(const int* __restrict__ ei) {
    bool is64 = ((ei[1] | ei[3] | ei[5] | ei[7] | ei[9] | ei[11] | ei[13] | ei[15]) == 0);
    int stride = gridDim.x * blockDim.x;
    for (int i = blockIdx.x * blockDim.x + threadIdx.x; i < NEDGE; i += stride) {
        int s, d;
        if (is64) {
            const long long* p = (const long long*)ei;
            s = (int)p[i];
            d = (int)p[NEDGE + i];
        } else {
            s = ei[i];
            d = ei[NEDGE + i];
        }
        g_src[i] = s;
        g_dst[i] = d;
    }
}

// ---------------- 2) transposes + zero stats ------------------------------------
__global__ void k_misc(const float* __restrict__ We, const float* __restrict__ W1,
                       const float* __restrict__ W2) {
    int stride = gridDim.x * blockDim.x;
    int t0 = blockIdx.x * blockDim.x + threadIdx.x;
    for (int i = t0; i < DE * DD; i += stride) { int k = i / DD, j = i % DD; g_WeT[i] = We[j * DE + k]; }
    for (int i = t0; i < DD * HH; i += stride) { int k = i / HH, j = i % HH; g_W1T[i] = W1[j * DD + k]; }
    for (int i = t0; i < HH * DD; i += stride) { int k = i / DD, j = i % DD; g_W2T[i] = W2[j * HH + k]; }
    for (int i = t0; i < HH; i += stride) { g_sum1[i] = 0.f; g_sq1[i] = 0.f; }
    for (int i = t0; i < DD; i += stride) { g_sum2[i] = 0.f; g_sq2[i] = 0.f; }
}

// ---------------- 3) hpre = (1+eps) * x -----------------------------------------
__global__ void k_hpre(const float* __restrict__ x, const float* __restrict__ epsp) {
    float c = 1.0f + *epsp;
    int stride = gridDim.x * blockDim.x;
    const float4* x4 = (const float4*)x;
    float4* h4 = (float4*)g_hpre;
    for (int i = blockIdx.x * blockDim.x + threadIdx.x; i < NNODE * DD / 4; i += stride) {
        float4 v = x4[i];
        v.x *= c; v.y *= c; v.z *= c; v.w *= c;
        h4[i] = v;
    }
}

// ---------------- 4) edge kernel: FFMA2 GEMM (8x8 tile, 2 CTAs/SM) ---------------
// EXACT r14 structure (best: 303us) with ONE change: A rows padded to 80 floats
// and rotated by ((row>>3)&3)*4 so the warp's two broadcast rows (8 apart,
// previously same-bank: 8*64 = 512 = 0 mod 32) land on disjoint bank quads ->
// A loads go 2 wavefronts -> 1. B layout/loads/epilogue byte-identical to r14.
#define AEPAD 80
#define SM_A_FLOATS (128 * AEPAD)                       // 10240
#define SM_IDX_F (SM_A_FLOATS + DE * DD)
#define SM_EDGE_TOTAL ((SM_IDX_F + 256) * 4)            // 74752 B; x2 CTAs = 149.5 KB

__global__ __launch_bounds__(256, 2) void k_edge(const float* __restrict__ ea,
                                                 const float* __restrict__ x,
                                                 const float* __restrict__ be) {
    extern __shared__ float sm[];
    float* sEA = sm;                       // [128][80], rotated rows
    float* sW  = sm + SM_A_FLOATS;         // [64][128]  (WeT layout)
    int* sSrc = (int*)(sm + SM_IDX_F);
    int* sDst = sSrc + 128;

    int tid = threadIdx.x;
    int e0 = blockIdx.x * 128;

    // A fill: coalesced read, rotated store
#pragma unroll
    for (int r = 0; r < 8; r++) {
        int i = tid + 256 * r;             // 0..2047 float4s
        int row = i >> 4, c4 = i & 15;
        float4 v = *(const float4*)(ea + (size_t)e0 * DE + i * 4);
        *(float4*)&sEA[row * AEPAD + ((row >> 3) & 3) * 4 + c4 * 4] = v;
    }
    const float4* gW = (const float4*)g_WeT;
    float4* w4 = (float4*)sW;
#pragma unroll
    for (int r = 0; r < 8; r++) w4[tid + 256 * r] = gW[tid + 256 * r];
    if (tid < 128) { sSrc[tid] = g_src[e0 + tid]; sDst[tid] = g_dst[e0 + tid]; }
    __syncthreads();

    int tx8 = (tid & 15) * 8;   // output group
    int ty = tid >> 4;          // edge group (8 edges at ty*8)
    int ty8 = ty * 8;
    unsigned long long acc[8][4];
#pragma unroll
    for (int i = 0; i < 8; i++)
#pragma unroll
        for (int j = 0; j < 4; j++) acc[i][j] = 0ull;

    // all 8 rows of this thread are in group ty -> constant rotation (ty&3)*4
    const float* aBase = sEA + ty8 * AEPAD + (ty & 3) * 4;

#pragma unroll
    for (int k = 0; k < DE; k += 4) {
        // B rows k..k+3 for this thread's 8 columns: 16 ull (32 regs), loop-invariant
        unsigned long long b[4][4];
#pragma unroll
        for (int kk = 0; kk < 4; kk++) {
            const unsigned long long* bp = (const unsigned long long*)&sW[(k + kk) * DD + tx8];
            b[kk][0] = bp[0]; b[kk][1] = bp[1]; b[kk][2] = bp[2]; b[kk][3] = bp[3];
        }
#pragma unroll
        for (int i = 0; i < 8; i++) {
            float4 a4 = *(const float4*)(aBase + i * AEPAD + k);
#pragma unroll
            for (int kk = 0; kk < 4; kk++) {
                unsigned long long a2 = bcast2(((const float*)&a4)[kk]);
                ffma2(acc[i][0], a2, b[kk][0]);
                ffma2(acc[i][1], a2, b[kk][1]);
                ffma2(acc[i][2], a2, b[kk][2]);
                ffma2(acc[i][3], a2, b[kk][3]);
            }
        }
    }

    float4 be0 = *(const float4*)(be + tx8);
    float4 be1 = *(const float4*)(be + tx8 + 4);
#pragma unroll
    for (int i = 0; i < 8; i++) {
        int el = ty8 + i;
        int s = sSrc[el];
        int d = sDst[el];
        const float4* xr = (const float4*)(x + (size_t)s * DD + tx8);
        float4 x0 = xr[0], x1 = xr[1];
        float2 p0 = up2(acc[i][0]), p1 = up2(acc[i][1]);
        float2 p2 = up2(acc[i][2]), p3 = up2(acc[i][3]);
        float* dptr = g_hpre + (size_t)d * DD + tx8;
        red_add_v4(dptr,
                   fmaxf(p0.x + x0.x + be0.x, 0.f),
                   fmaxf(p0.y + x0.y + be0.y, 0.f),
                   fmaxf(p1.x + x0.z + be0.z, 0.f),
                   fmaxf(p1.y + x0.w + be0.w, 0.f));
        red_add_v4(dptr + 4,
                   fmaxf(p2.x + x1.x + be1.x, 0.f),
                   fmaxf(p2.y + x1.y + be1.y, 0.f),
                   fmaxf(p3.x + x1.z + be1.z, 0.f),
                   fmaxf(p3.y + x1.w + be1.w, 0.f));
    }
}

// ---------------- 5) GEMM1: y1 = hpre @ W1^T + b1, accumulate BN stats ----------
__global__ __launch_bounds__(256, 2) void k_gemm1(const float* __restrict__ bias) {
    __shared__ float As[128 * 36];
    __shared__ float Bs[32 * 128];
    __shared__ float sSum[128];
    __shared__ float sSq[128];
    int tid = threadIdx.x;
    int m0 = blockIdx.x * 128;
    int n0 = blockIdx.y * 128;
    int tx8 = (tid & 15) * 8;
    int ty8 = (tid >> 4) * 8;
    unsigned long long acc[8][4];
#pragma unroll
    for (int i = 0; i < 8; i++)
#pragma unroll
        for (int j = 0; j < 4; j++) acc[i][j] = 0ull;

    for (int kc = 0; kc < DD; kc += 32) {
#pragma unroll
        for (int r = 0; r < 4; r++) {
            int idx = tid + 256 * r;
            int row = idx >> 3, c4 = idx & 7;
            int m = m0 + row;
            float4 v = make_float4(0.f, 0.f, 0.f, 0.f);
            if (m < NNODE) v = *(const float4*)&g_hpre[(size_t)m * DD + kc + c4 * 4];
            *(float4*)&As[row * 36 + c4 * 4] = v;
        }
#pragma unroll
        for (int r = 0; r < 4; r++) {
            int idx = tid + 256 * r;
            int k = idx >> 5, c4 = idx & 31;
            *(float4*)&Bs[k * 128 + c4 * 4] = *(const float4*)&g_W1T[(size_t)(kc + k) * HH + n0 + c4 * 4];
        }
        __syncthreads();
#pragma unroll
        for (int k = 0; k < 32; k += 4) {
            unsigned long long b[4][4];
#pragma unroll
            for (int kk = 0; kk < 4; kk++) {
                const unsigned long long* bp = (const unsigned long long*)&Bs[(k + kk) * 128 + tx8];
                b[kk][0] = bp[0]; b[kk][1] = bp[1]; b[kk][2] = bp[2]; b[kk][3] = bp[3];
            }
#pragma unroll
            for (int i = 0; i < 8; i++) {
                float4 a4 = *(const float4*)&As[(ty8 + i) * 36 + k];
#pragma unroll
                for (int kk = 0; kk < 4; kk++) {
                    unsigned long long a2 = bcast2(((const float*)&a4)[kk]);
                    ffma2(acc[i][0], a2, b[kk][0]);
                    ffma2(acc[i][1], a2, b[kk][1]);
                    ffma2(acc[i][2], a2, b[kk][2]);
                    ffma2(acc[i][3], a2, b[kk][3]);
                }
            }
        }
        __syncthreads();
    }

    float4 bb0 = *(const float4*)&bias[n0 + tx8];
    float4 bb1 = *(const float4*)&bias[n0 + tx8 + 4];
    float bv[8] = {bb0.x, bb0.y, bb0.z, bb0.w, bb1.x, bb1.y, bb1.z, bb1.w};
    float lsum[8], lsq[8];
#pragma unroll
    for (int j = 0; j < 8; j++) { lsum[j] = 0.f; lsq[j] = 0.f; }
#pragma unroll
    for (int i = 0; i < 8; i++) {
        int m = m0 + ty8 + i;
        if (m < NNODE) {
            float2 pr[4] = {up2(acc[i][0]), up2(acc[i][1]), up2(acc[i][2]), up2(acc[i][3])};
            float v[8];
#pragma unroll
            for (int j = 0; j < 8; j++) {
                float a = (j & 1) ? pr[j >> 1].y : pr[j >> 1].x;
                v[j] = a + bv[j];
                lsum[j] += v[j];
                lsq[j] += v[j] * v[j];
            }
            float4* o = (float4*)&g_y1[(size_t)m * HH + n0 + tx8];
            o[0] = make_float4(v[0], v[1], v[2], v[3]);
            o[1] = make_float4(v[4], v[5], v[6], v[7]);
        }
    }
    if (tid < 128) { sSum[tid] = 0.f; sSq[tid] = 0.f; }
    __syncthreads();
#pragma unroll
    for (int j = 0; j < 8; j++) {
        atomicAdd(&sSum[tx8 + j], lsum[j]);
        atomicAdd(&sSq[tx8 + j], lsq[j]);
    }
    __syncthreads();
    if (tid < 128) {
        atomicAdd(&g_sum1[n0 + tid], sSum[tid]);
        atomicAdd(&g_sq1[n0 + tid], sSq[tid]);
    }
}

// ---------------- 6) fold BN1 stats into scale/shift ----------------------------
__global__ void k_stat1(const float* __restrict__ g, const float* __restrict__ beta) {
    int j = threadIdx.x;
    if (j < HH) {
        float mu = g_sum1[j] / (float)NNODE;
        float var = g_sq1[j] / (float)NNODE - mu * mu;
        float sc = g[j] * rsqrtf(var + BN_EPS);
        g_scale1[j] = sc;
        g_shift1[j] = beta[j] - mu * sc;
    }
}

// ---------------- 7) GEMM2: out = relu(bn1(y1)) @ W2^T + b2, accumulate stats ---
__global__ __launch_bounds__(256, 2) void k_gemm2(const float* __restrict__ bias,
                                                  float* __restrict__ out) {
    __shared__ float As[128 * 36];
    __shared__ float Bs[32 * 128];
    __shared__ float sSum[128];
    __shared__ float sSq[128];
    int tid = threadIdx.x;
    int m0 = blockIdx.x * 128;
    int tx8 = (tid & 15) * 8;
    int ty8 = (tid >> 4) * 8;
    unsigned long long acc[8][4];
#pragma unroll
    for (int i = 0; i < 8; i++)
#pragma unroll
        for (int j = 0; j < 4; j++) acc[i][j] = 0ull;

    for (int kc = 0; kc < HH; kc += 32) {
#pragma unroll
        for (int r = 0; r < 4; r++) {
            int idx = tid + 256 * r;
            int row = idx >> 3, c4 = idx & 7;
            int m = m0 + row;
            int col = kc + c4 * 4;
            float4 v = make_float4(0.f, 0.f, 0.f, 0.f);
            if (m < NNODE) v = *(const float4*)&g_y1[(size_t)m * HH + col];
            float4 sc = *(const float4*)&g_scale1[col];
            float4 sh = *(const float4*)&g_shift1[col];
            v.x = fmaxf(fmaf(v.x, sc.x, sh.x), 0.f);
            v.y = fmaxf(fmaf(v.y, sc.y, sh.y), 0.f);
            v.z = fmaxf(fmaf(v.z, sc.z, sh.z), 0.f);
            v.w = fmaxf(fmaf(v.w, sc.w, sh.w), 0.f);
            *(float4*)&As[row * 36 + c4 * 4] = v;
        }
#pragma unroll
        for (int r = 0; r < 4; r++) {
            int idx = tid + 256 * r;
            int k = idx >> 5, c4 = idx & 31;
            *(float4*)&Bs[k * 128 + c4 * 4] = *(const float4*)&g_W2T[(size_t)(kc + k) * DD + c4 * 4];
        }
        __syncthreads();
#pragma unroll
        for (int k = 0; k < 32; k += 4) {
            unsigned long long b[4][4];
#pragma unroll
            for (int kk = 0; kk < 4; kk++) {
                const unsigned long long* bp = (const unsigned long long*)&Bs[(k + kk) * 128 + tx8];
                b[kk][0] = bp[0]; b[kk][1] = bp[1]; b[kk][2] = bp[2]; b[kk][3] = bp[3];
            }
#pragma unroll
            for (int i = 0; i < 8; i++) {
                float4 a4 = *(const float4*)&As[(ty8 + i) * 36 + k];
#pragma unroll
                for (int kk = 0; kk < 4; kk++) {
                    unsigned long long a2 = bcast2(((const float*)&a4)[kk]);
                    ffma2(acc[i][0], a2, b[kk][0]);
                    ffma2(acc[i][1], a2, b[kk][1]);
                    ffma2(acc[i][2], a2, b[kk][2]);
                    ffma2(acc[i][3], a2, b[kk][3]);
                }
            }
        }
        __syncthreads();
    }

    float4 bb0 = *(const float4*)&bias[tx8];
    float4 bb1 = *(const float4*)&bias[tx8 + 4];
    float bv[8] = {bb0.x, bb0.y, bb0.z, bb0.w, bb1.x, bb1.y, bb1.z, bb1.w};
    float lsum[8], lsq[8];
#pragma unroll
    for (int j = 0; j < 8; j++) { lsum[j] = 0.f; lsq[j] = 0.f; }
#pragma unroll
    for (int i = 0; i < 8; i++) {
        int m = m0 + ty8 + i;
        if (m < NNODE) {
            float2 pr[4] = {up2(acc[i][0]), up2(acc[i][1]), up2(acc[i][2]), up2(acc[i][3])};
            float v[8];
#pragma unroll
            for (int j = 0; j < 8; j++) {
                float a = (j & 1) ? pr[j >> 1].y : pr[j >> 1].x;
                v[j] = a + bv[j];
                lsum[j] += v[j];
                lsq[j] += v[j] * v[j];
            }
            float4* o = (float4*)&out[(size_t)m * DD + tx8];
            o[0] = make_float4(v[0], v[1], v[2], v[3]);
            o[1] = make_float4(v[4], v[5], v[6], v[7]);
        }
    }
    if (tid < 128) { sSum[tid] = 0.f; sSq[tid] = 0.f; }
    __syncthreads();
#pragma unroll
    for (int j = 0; j < 8; j++) {
        atomicAdd(&sSum[tx8 + j], lsum[j]);
        atomicAdd(&sSq[tx8 + j], lsq[j]);
    }
    __syncthreads();
    if (tid < 128) {
        atomicAdd(&g_sum2[tid], sSum[tid]);
        atomicAdd(&g_sq2[tid], sSq[tid]);
    }
}

// ---------------- 8) fold BN2 stats --------------------------------------------
__global__ void k_stat2(const float* __restrict__ g, const float* __restrict__ beta) {
    int j = threadIdx.x;
    if (j < DD) {
        float mu = g_sum2[j] / (float)NNODE;
        float var = g_sq2[j] / (float)NNODE - mu * mu;
        float sc = g[j] * rsqrtf(var + BN_EPS);
        g_scale2[j] = sc;
        g_shift2[j] = beta[j] - mu * sc;
    }
}

// ---------------- 9) final elementwise: out = relu(bn2(out)) --------------------
__global__ void k_final(float* __restrict__ out) {
    int stride = gridDim.x * blockDim.x;
    float4* o4 = (float4*)out;
    for (int i = blockIdx.x * blockDim.x + threadIdx.x; i < NNODE * DD / 4; i += stride) {
        int col = (i & 31) * 4;
        float4 sc = *(const float4*)&g_scale2[col];
        float4 sh = *(const float4*)&g_shift2[col];
        float4 v = o4[i];
        v.x = fmaxf(fmaf(v.x, sc.x, sh.x), 0.f);
        v.y = fmaxf(fmaf(v.y, sc.y, sh.y), 0.f);
        v.z = fmaxf(fmaf(v.z, sc.z, sh.z), 0.f);
        v.w = fmaxf(fmaf(v.w, sc.w, sh.w), 0.f);
        o4[i] = v;
    }
}

// ---------------- launcher ------------------------------------------------------
extern "C" void kernel_launch(void* const* d_in, const int* in_sizes, int n_in,
                              void* d_out, int out_size) {
    const float* x   = (const float*)d_in[0];
    const int*   ei  = (const int*)d_in[1];
    const float* ea  = (const float*)d_in[2];
    const float* We  = (const float*)d_in[3];
    const float* be  = (const float*)d_in[4];
    const float* W1  = (const float*)d_in[5];
    const float* b1  = (const float*)d_in[6];
    const float* g1  = (const float*)d_in[7];
    const float* be1 = (const float*)d_in[8];
    const float* W2  = (const float*)d_in[9];
    const float* b2  = (const float*)d_in[10];
    const float* g2  = (const float*)d_in[11];
    const float* be2 = (const float*)d_in[12];
    const float* eps = (const float*)d_in[13];
    float* out = (float*)d_out;

    cudaFuncSetAttribute(k_edge, cudaFuncAttributeMaxDynamicSharedMemorySize, SM_EDGE_TOTAL);

    k_decode<<<1024, 256>>>(ei);
    k_misc<<<64, 256>>>(We, W1, W2);
    k_hpre<<<2048, 256>>>(x, eps);
    k_edge<<<NEDGE / 128, 256, SM_EDGE_TOTAL>>>(ea, x, be);
    dim3 g1grid((NNODE + 127) / 128, 2);
    k_gemm1<<<g1grid, 256>>>(b1);
    k_stat1<<<1, 256>>>(g1, be1);
    k_gemm2<<<(NNODE + 127) / 128, 256>>>(b2, out);
    k_stat2<<<1, 128>>>(g2, be2);
    k_final<<<2048, 256>>>(out);
}